// round 7
// baseline (speedup 1.0000x reference)
#include <cuda_runtime.h>
#include <math.h>
#include <float.h>

#define BB 2
#define NN 4096
#define CC 64
#define BN (BB*NN)

typedef unsigned long long u64;

// ---------------- device scratch (no allocations allowed) ----------------
__device__ float g_f1a[BN*CC];       // point-major [b*N+n][d]
__device__ float g_f2a[BN*CC];
__device__ float g_f2b[BN*CC];
__device__ float g_f1b[BN*CC];
__device__ float g_kn[2][CC*BN];     // channel-major [s][(b*64+c)*NN + n]
__device__ float4 g_xyz[2][BN];      // (x,y,z,|p|^2)
__device__ int   g_idx[2*BN*16];     // [dir][b][n][16]: 0..7 cosine, 8..15 euclid

__device__ __forceinline__ float leaky(float x){ return fmaxf(x, 0.1f*x); }

// ---- packed fp32x2 helpers (FFMA2: ptxas never emits these from C++) ----
__device__ __forceinline__ u64 pk2(float lo, float hi){
  u64 r; asm("mov.b64 %0, {%1, %2};" : "=l"(r) : "f"(lo), "f"(hi)); return r;
}
__device__ __forceinline__ void fma2(u64 &d, u64 a, u64 b){
  asm("fma.rn.f32x2 %0, %1, %2, %0;" : "+l"(d) : "l"(a), "l"(b));
}
__device__ __forceinline__ float2 up2(u64 v){
  float2 r; asm("mov.b64 {%0, %1}, %2;" : "=f"(r.x), "=f"(r.y) : "l"(v)); return r;
}

#define INSERT8(dA, iA, dval, mval)                                         \
  if ((dval) < dA[7]) {                                                     \
    dA[7] = (dval); iA[7] = (mval);                                         \
    _Pragma("unroll")                                                       \
    for (int _i = 7; _i > 0; _i--) {                                        \
      if (dA[_i] < dA[_i-1]) {                                              \
        float _tv = dA[_i]; dA[_i] = dA[_i-1]; dA[_i-1] = _tv;              \
        int   _ti = iA[_i]; iA[_i] = iA[_i-1]; iA[_i-1] = _ti;              \
      }                                                                     \
    }                                                                       \
  }

// ---------------- 1x1 conv transforms: f1a,f2a,f2b,f1b -------------------
__global__ __launch_bounds__(256) void k_transform(
    const float* __restrict__ feat1, const float* __restrict__ feat2,
    const float* __restrict__ W11, const float* __restrict__ b11,
    const float* __restrict__ W22, const float* __restrict__ b22)
{
  int n0 = blockIdx.x * 64, b = blockIdx.y, combo = blockIdx.z;
  const float* src  = (combo == 0 || combo == 3) ? feat1 : feat2;
  const float* W    = (combo == 0 || combo == 2) ? W11 : W22;
  const float* bias = (combo == 0 || combo == 2) ? b11 : b22;
  float* dst = (combo == 0) ? g_f1a : (combo == 1) ? g_f2a : (combo == 2) ? g_f2b : g_f1b;

  __shared__ float sF[64*65];   // [c][nn]
  __shared__ float sWT[64*65];  // [c][d]
  __shared__ float sB[64];
  int t = threadIdx.x;

  #pragma unroll
  for (int i = 0; i < 16; i++) {
    int idx = t + i*256;
    int hi = idx >> 6, lo = idx & 63;
    sF[hi*65 + lo]  = src[(b*64 + hi)*NN + n0 + lo];
    sWT[lo*65 + hi] = W[hi*64 + lo];
  }
  if (t < 64) sB[t] = bias[t];
  __syncthreads();

  int d = t & 63, g = t >> 6;
  for (int i = 0; i < 16; i++) {
    int nn = g*16 + i;
    float acc = sB[d];
    #pragma unroll
    for (int c = 0; c < 64; c++) acc += sWT[c*65 + d] * sF[c*65 + nn];
    dst[(b*NN + n0 + nn)*64 + d] = acc;
  }
}

// ------- normalize knn features (stay channel-major, just scale) ----------
__global__ __launch_bounds__(256) void k_normalize(
    const float* __restrict__ knn1, const float* __restrict__ knn2)
{
  int n0 = blockIdx.x * 64, b = blockIdx.y, s = blockIdx.z;
  const float* src = s ? knn2 : knn1;
  __shared__ float sF[64*65];
  __shared__ float sInv[64];
  int t = threadIdx.x;

  #pragma unroll
  for (int i = 0; i < 16; i++) {
    int idx = t + i*256;
    int c = idx >> 6, x = idx & 63;
    sF[c*65 + x] = src[(b*64 + c)*NN + n0 + x];
  }
  __syncthreads();
  if (t < 64) {
    float sum = 0.f;
    #pragma unroll
    for (int c = 0; c < 64; c++) { float v = sF[c*65 + t]; sum += v*v; }
    sInv[t] = 1.0f / sqrtf(sum + 1e-8f);
  }
  __syncthreads();
  #pragma unroll
  for (int i = 0; i < 16; i++) {
    int idx = t + i*256;
    int c = idx >> 6, x = idx & 63;
    g_kn[s][(b*64 + c)*NN + n0 + x] = sF[c*65 + x] * sInv[x];
  }
}

// ---------------- xyz transpose + squared norms ---------------------------
__global__ __launch_bounds__(256) void k_xyz(
    const float* __restrict__ pc1, const float* __restrict__ pc2)
{
  int b = blockIdx.y, s = blockIdx.z;
  const float* pc = s ? pc2 : pc1;
  int n = blockIdx.x*256 + threadIdx.x;
  float x = pc[(b*3 + 0)*NN + n];
  float y = pc[(b*3 + 1)*NN + n];
  float z = pc[(b*3 + 2)*NN + n];
  g_xyz[s][b*NN + n] = make_float4(x, y, z, x*x + y*y + z*z);
}

// --------- cosine KNN: 64q x 128m tile, FFMA2 outer-product + scan --------
// smem (floats): sQ[64c][68] 4352 | sD[64c][132] 8448 | dist[64q][132] 8448
//   total 21248 floats = 84992 B
__global__ __launch_bounds__(256, 2) void k_knn_cos()
{
  extern __shared__ float smem[];
  float* sQ   = smem;
  float* sD   = smem + 4352;
  float* dist = smem + 12800;

  int dir = blockIdx.z, b = blockIdx.y;
  int qbase = blockIdx.x * 64;
  const float* Qg = dir ? g_kn[1] : g_kn[0];
  const float* Dg = dir ? g_kn[0] : g_kn[1];

  int t = threadIdx.x;
  int tq = t >> 4, tm = t & 15;   // GEMM: 4 queries x 8 candidates per thread
  int sq = t >> 2, sl = t & 3;    // scan: 4 threads per query

  // fill sQ [c][q]
  {
    int c0 = t >> 4, m4 = t & 15;
    #pragma unroll
    for (int i = 0; i < 4; i++) {
      int c = c0 + 16*i;
      *(float4*)&sQ[c*68 + m4*4] =
        *(const float4*)&Qg[(b*64 + c)*NN + qbase + m4*4];
    }
  }

  float dC[8]; int iC[8];
  #pragma unroll
  for (int i = 0; i < 8; i++) { dC[i] = FLT_MAX; iC[i] = -1; }

  for (int mb = 0; mb < NN; mb += 128) {
    __syncthreads();
    // fill sD [c][m] : 64 rows x 128 floats
    {
      int c0 = t >> 5, c4 = t & 31;
      #pragma unroll
      for (int i = 0; i < 8; i++) {
        int c = c0 + 8*i;
        *(float4*)&sD[c*132 + c4*4] =
          *(const float4*)&Dg[(b*64 + c)*NN + mb + c4*4];
      }
    }
    __syncthreads();

    u64 acc[4][4];
    #pragma unroll
    for (int i = 0; i < 4; i++)
      #pragma unroll
      for (int j = 0; j < 4; j++) acc[i][j] = 0ULL;

    #pragma unroll 4
    for (int c = 0; c < 64; c++) {
      float4 qf = *(const float4*)&sQ[c*68 + tq*4];
      ulonglong2 m01 = *(const ulonglong2*)&sD[c*132 + tm*8];
      ulonglong2 m23 = *(const ulonglong2*)&sD[c*132 + tm*8 + 4];
      u64 q0 = pk2(qf.x, qf.x), q1 = pk2(qf.y, qf.y);
      u64 q2 = pk2(qf.z, qf.z), q3 = pk2(qf.w, qf.w);
      fma2(acc[0][0], q0, m01.x); fma2(acc[0][1], q0, m01.y);
      fma2(acc[0][2], q0, m23.x); fma2(acc[0][3], q0, m23.y);
      fma2(acc[1][0], q1, m01.x); fma2(acc[1][1], q1, m01.y);
      fma2(acc[1][2], q1, m23.x); fma2(acc[1][3], q1, m23.y);
      fma2(acc[2][0], q2, m01.x); fma2(acc[2][1], q2, m01.y);
      fma2(acc[2][2], q2, m23.x); fma2(acc[2][3], q2, m23.y);
      fma2(acc[3][0], q3, m01.x); fma2(acc[3][1], q3, m01.y);
      fma2(acc[3][2], q3, m23.x); fma2(acc[3][3], q3, m23.y);
    }

    // dist = 1 - dot
    #pragma unroll
    for (int qi = 0; qi < 4; qi++) {
      float2 p0 = up2(acc[qi][0]), p1 = up2(acc[qi][1]);
      float2 p2v = up2(acc[qi][2]), p3 = up2(acc[qi][3]);
      int ro = (tq*4 + qi)*132 + tm*8;
      *(float4*)&dist[ro]     = make_float4(1.f-p0.x, 1.f-p0.y, 1.f-p1.x, 1.f-p1.y);
      *(float4*)&dist[ro + 4] = make_float4(1.f-p2v.x, 1.f-p2v.y, 1.f-p3.x, 1.f-p3.y);
    }
    __syncthreads();

    // scan: thread (sq, sl) handles candidates sl*32 .. sl*32+31 (ascending)
    #pragma unroll
    for (int i4 = 0; i4 < 8; i4++) {
      float4 dv = *(const float4*)&dist[sq*132 + sl*32 + i4*4];
      int m0 = mb + sl*32 + i4*4;
      INSERT8(dC, iC, dv.x, m0+0);
      INSERT8(dC, iC, dv.y, m0+1);
      INSERT8(dC, iC, dv.z, m0+2);
      INSERT8(dC, iC, dv.w, m0+3);
    }
  }

  // final merge: 4 sorted runs of 8 per query -> top-8
  __syncthreads();
  float* mD = dist;
  int*   mI = (int*)(dist + 2048);
  #pragma unroll
  for (int i = 0; i < 8; i++) {
    mD[(sq*4 + sl)*8 + i] = dC[i];
    mI[(sq*4 + sl)*8 + i] = iC[i];
  }
  __syncthreads();
  if (t < 64) {
    int base = t*32;
    int gb = ((dir*BB + b)*NN + qbase + t)*16;
    for (int r = 0; r < 8; r++) {
      float bd = FLT_MAX; int bs = 0;
      #pragma unroll
      for (int s2 = 0; s2 < 32; s2++) {
        float v = mD[base + s2];
        if (v < bd) { bd = v; bs = s2; }
      }
      g_idx[gb + r] = mI[base + bs];
      mD[base + bs] = FLT_MAX;
    }
  }
}

// --------- euclid KNN: 4 threads/query, blocked ranges, smem merge --------
__global__ __launch_bounds__(256) void k_euclid()
{
  int dir = blockIdx.z, b = blockIdx.y;
  int qbase = blockIdx.x * 64;
  const float4* Qx = dir ? g_xyz[1] : g_xyz[0];
  const float4* Dx = dir ? g_xyz[0] : g_xyz[1];
  int t = threadIdx.x;
  int ql = t >> 2, sl = t & 3;
  int q = qbase + ql;

  float4 qx = Qx[b*NN + q];
  float dE[8]; int iE[8];
  #pragma unroll
  for (int i = 0; i < 8; i++) { dE[i] = FLT_MAX; iE[i] = -1; }

  const float4* base = &Dx[b*NN + sl*1024];
  #pragma unroll 4
  for (int i = 0; i < 1024; i++) {
    float4 d = __ldg(&base[i]);
    float de = qx.w + d.w - 2.0f*(qx.x*d.x + qx.y*d.y + qx.z*d.z);
    INSERT8(dE, iE, de, sl*1024 + i);
  }

  __shared__ float mD[2048];
  __shared__ int   mI[2048];
  #pragma unroll
  for (int i = 0; i < 8; i++) { mD[t*8 + i] = dE[i]; mI[t*8 + i] = iE[i]; }
  __syncthreads();
  if (t < 64) {
    int mb = t*32;
    int gb = ((dir*BB + b)*NN + qbase + t)*16 + 8;
    for (int r = 0; r < 8; r++) {
      float bd = FLT_MAX; int bs = 0;
      #pragma unroll
      for (int s2 = 0; s2 < 32; s2++) {
        float v = mD[mb + s2];
        if (v < bd) { bd = v; bs = s2; }
      }
      g_idx[gb + r] = mI[mb + bs];
      mD[mb + bs] = FLT_MAX;
    }
  }
}

// ------ gather + pos-MLP + 2x MLP (FFMA2 register-blocked) + maxpool ------
// 8 queries/block -> 128 rows, column-major buffers, row stride 136.
// smem (floats): sW1 4352 | sW2 4352 | bufA 8704 | bufB 8704 | sP1 512
//   | sPos 256 | sB1 64 | sB2 64 | sDir 512 | sNb 128 = 27648 (110592 B)
__global__ __launch_bounds__(256, 2) void k_mlp(
    const float* __restrict__ Wpos, const float* __restrict__ bpos,
    const float* __restrict__ Wm1,  const float* __restrict__ b1,
    const float* __restrict__ Wm2,  const float* __restrict__ b2,
    float* __restrict__ out)
{
  extern __shared__ float sm[];
  float* sW1  = sm;
  float* sW2  = sm + 4352;
  float* bufA = sm + 8704;
  float* bufB = sm + 17408;
  float* sP1  = sm + 26112;
  float4* sPos = (float4*)(sm + 26624);
  float* sB1  = sm + 26880;
  float* sB2  = sm + 26944;
  float4* sDir = (float4*)(sm + 27008);
  int*   sNb  = (int*)(sm + 27520);

  int dir = blockIdx.z, b = blockIdx.y;
  int n0 = blockIdx.x * 8;
  const float* p1 = dir ? g_f2b : g_f1a;
  const float* p2 = dir ? g_f1b : g_f2a;
  const float4* Qx = dir ? g_xyz[1] : g_xyz[0];
  const float4* Dx = dir ? g_xyz[0] : g_xyz[1];

  int t = threadIdx.x;

  // load both weights transposed: sW[c*68+e] = W[e*64+c]
  #pragma unroll
  for (int i = 0; i < 16; i++) {
    int idx = t + i*256;
    int e = idx >> 6, c = idx & 63;
    sW1[c*68 + e] = Wm1[idx];
    sW2[c*68 + e] = Wm2[idx];
  }
  if (t < 64) {
    sPos[t] = make_float4(Wpos[t*3], Wpos[t*3+1], Wpos[t*3+2], bpos[t]);
    sB1[t] = b1[t];
    sB2[t] = b2[t];
  }
  #pragma unroll
  for (int i = 0; i < 2; i++) {
    int idx = t + i*256;
    int q = idx >> 6, d = idx & 63;
    sP1[idx] = p1[(b*NN + n0 + q)*64 + d];
  }
  if (t < 128) {
    int q = t >> 4, k = t & 15;
    int nb = g_idx[((dir*BB + b)*NN + n0 + q)*16 + k];
    sNb[t] = nb;
    float4 dxv = Dx[b*NN + nb], qxv = Qx[b*NN + n0 + q];
    sDir[t] = make_float4(dxv.x - qxv.x, dxv.y - qxv.y, dxv.z - qxv.z, 0.f);
  }
  __syncthreads();

  // stage 0: bufA[d][row] = leaky(g2 + p1 + pos)
  {
    int row = t & 127, half = t >> 7;
    int nb = sNb[row];
    int q = row >> 4;
    float4 dv = sDir[row];
    const float4* p2row = (const float4*)&p2[(b*NN + nb)*64] + half*8;
    const float* p1row = &sP1[q*64 + half*32];
    #pragma unroll
    for (int j = 0; j < 8; j++) {
      int d = half*32 + j*4;
      float4 g = p2row[j];
      float4 w0 = sPos[d+0], w1 = sPos[d+1], w2 = sPos[d+2], w3 = sPos[d+3];
      float v0 = g.x + p1row[j*4+0] + (dv.x*w0.x + dv.y*w0.y + dv.z*w0.z + w0.w);
      float v1 = g.y + p1row[j*4+1] + (dv.x*w1.x + dv.y*w1.y + dv.z*w1.z + w1.w);
      float v2 = g.z + p1row[j*4+2] + (dv.x*w2.x + dv.y*w2.y + dv.z*w2.z + w2.w);
      float v3 = g.w + p1row[j*4+3] + (dv.x*w3.x + dv.y*w3.y + dv.z*w3.z + w3.w);
      bufA[(d+0)*136 + row] = leaky(v0);
      bufA[(d+1)*136 + row] = leaky(v1);
      bufA[(d+2)*136 + row] = leaky(v2);
      bufA[(d+3)*136 + row] = leaky(v3);
    }
  }
  __syncthreads();

  int rq = t >> 4, tm = t & 15;
  int r0 = rq*8, e0 = tm*4;

  // stage 1: bufB[e][row] = leaky(sum_c bufA[c][row]*W1[e][c] + b1)
  {
    u64 acc[4][4];
    #pragma unroll
    for (int i = 0; i < 4; i++)
      #pragma unroll
      for (int j = 0; j < 4; j++) acc[i][j] = 0ULL;
    #pragma unroll 4
    for (int c = 0; c < 64; c++) {
      float4 wf = *(const float4*)&sW1[c*68 + e0];
      ulonglong2 ra = *(const ulonglong2*)&bufA[c*136 + r0];
      ulonglong2 rb = *(const ulonglong2*)&bufA[c*136 + r0 + 4];
      u64 w0 = pk2(wf.x, wf.x), w1 = pk2(wf.y, wf.y);
      u64 w2 = pk2(wf.z, wf.z), w3 = pk2(wf.w, wf.w);
      fma2(acc[0][0], ra.x, w0); fma2(acc[0][1], ra.x, w1);
      fma2(acc[0][2], ra.x, w2); fma2(acc[0][3], ra.x, w3);
      fma2(acc[1][0], ra.y, w0); fma2(acc[1][1], ra.y, w1);
      fma2(acc[1][2], ra.y, w2); fma2(acc[1][3], ra.y, w3);
      fma2(acc[2][0], rb.x, w0); fma2(acc[2][1], rb.x, w1);
      fma2(acc[2][2], rb.x, w2); fma2(acc[2][3], rb.x, w3);
      fma2(acc[3][0], rb.y, w0); fma2(acc[3][1], rb.y, w1);
      fma2(acc[3][2], rb.y, w2); fma2(acc[3][3], rb.y, w3);
    }
    #pragma unroll
    for (int j = 0; j < 4; j++) {
      float bb = sB1[e0 + j];
      float2 v01 = up2(acc[0][j]), v23 = up2(acc[1][j]);
      float2 v45 = up2(acc[2][j]), v67 = up2(acc[3][j]);
      float4 lo = make_float4(leaky(v01.x+bb), leaky(v01.y+bb),
                              leaky(v23.x+bb), leaky(v23.y+bb));
      float4 hi = make_float4(leaky(v45.x+bb), leaky(v45.y+bb),
                              leaky(v67.x+bb), leaky(v67.y+bb));
      *(float4*)&bufB[(e0+j)*136 + r0]     = lo;
      *(float4*)&bufB[(e0+j)*136 + r0 + 4] = hi;
    }
  }
  __syncthreads();

  // stage 2: bufA[e][row] = leaky(sum_c bufB[c][row]*W2[e][c] + b2)
  {
    u64 acc[4][4];
    #pragma unroll
    for (int i = 0; i < 4; i++)
      #pragma unroll
      for (int j = 0; j < 4; j++) acc[i][j] = 0ULL;
    #pragma unroll 4
    for (int c = 0; c < 64; c++) {
      float4 wf = *(const float4*)&sW2[c*68 + e0];
      ulonglong2 ra = *(const ulonglong2*)&bufB[c*136 + r0];
      ulonglong2 rb = *(const ulonglong2*)&bufB[c*136 + r0 + 4];
      u64 w0 = pk2(wf.x, wf.x), w1 = pk2(wf.y, wf.y);
      u64 w2 = pk2(wf.z, wf.z), w3 = pk2(wf.w, wf.w);
      fma2(acc[0][0], ra.x, w0); fma2(acc[0][1], ra.x, w1);
      fma2(acc[0][2], ra.x, w2); fma2(acc[0][3], ra.x, w3);
      fma2(acc[1][0], ra.y, w0); fma2(acc[1][1], ra.y, w1);
      fma2(acc[1][2], ra.y, w2); fma2(acc[1][3], ra.y, w3);
      fma2(acc[2][0], rb.x, w0); fma2(acc[2][1], rb.x, w1);
      fma2(acc[2][2], rb.x, w2); fma2(acc[2][3], rb.x, w3);
      fma2(acc[3][0], rb.y, w0); fma2(acc[3][1], rb.y, w1);
      fma2(acc[3][2], rb.y, w2); fma2(acc[3][3], rb.y, w3);
    }
    #pragma unroll
    for (int j = 0; j < 4; j++) {
      float bb = sB2[e0 + j];
      float2 v01 = up2(acc[0][j]), v23 = up2(acc[1][j]);
      float2 v45 = up2(acc[2][j]), v67 = up2(acc[3][j]);
      float4 lo = make_float4(leaky(v01.x+bb), leaky(v01.y+bb),
                              leaky(v23.x+bb), leaky(v23.y+bb));
      float4 hi = make_float4(leaky(v45.x+bb), leaky(v45.y+bb),
                              leaky(v67.x+bb), leaky(v67.y+bb));
      *(float4*)&bufA[(e0+j)*136 + r0]     = lo;
      *(float4*)&bufA[(e0+j)*136 + r0 + 4] = hi;
    }
  }
  __syncthreads();

  // maxpool over k (16 contiguous rows per query) + store [e][n]
  #pragma unroll
  for (int i = 0; i < 2; i++) {
    int o = t + i*256;
    int q = o & 7, e = o >> 3;
    const float4* r = (const float4*)&bufA[e*136 + q*16];
    float4 v0 = r[0], v1 = r[1], v2 = r[2], v3 = r[3];
    float m = fmaxf(fmaxf(fmaxf(v0.x, v0.y), fmaxf(v0.z, v0.w)),
                    fmaxf(fmaxf(v1.x, v1.y), fmaxf(v1.z, v1.w)));
    m = fmaxf(m, fmaxf(fmaxf(fmaxf(v2.x, v2.y), fmaxf(v2.z, v2.w)),
                       fmaxf(fmaxf(v3.x, v3.y), fmaxf(v3.z, v3.w))));
    out[dir*(BB*64*NN) + b*(64*NN) + e*NN + (n0 + q)] = m;
  }
}

// ---------------- launch ---------------------------------------------------
extern "C" void kernel_launch(void* const* d_in, const int* in_sizes, int n_in,
                              void* d_out, int out_size)
{
  const float* pc1   = (const float*)d_in[0];
  const float* pc2   = (const float*)d_in[1];
  const float* feat1 = (const float*)d_in[2];
  const float* feat2 = (const float*)d_in[3];
  const float* knn1  = (const float*)d_in[4];
  const float* knn2  = (const float*)d_in[5];
  const float* W11   = (const float*)d_in[6];
  const float* b11   = (const float*)d_in[7];
  const float* W22   = (const float*)d_in[8];
  const float* b22   = (const float*)d_in[9];
  const float* Wpos  = (const float*)d_in[10];
  const float* bpos  = (const float*)d_in[11];
  const float* Wm1   = (const float*)d_in[12];
  const float* bm1   = (const float*)d_in[13];
  const float* Wm2   = (const float*)d_in[14];
  const float* bm2   = (const float*)d_in[15];
  float* out = (float*)d_out;

  cudaFuncSetAttribute(k_knn_cos, cudaFuncAttributeMaxDynamicSharedMemorySize, 84992);
  cudaFuncSetAttribute(k_mlp, cudaFuncAttributeMaxDynamicSharedMemorySize, 110592);

  k_transform<<<dim3(64, 2, 4), 256>>>(feat1, feat2, W11, b11, W22, b22);
  k_normalize<<<dim3(64, 2, 2), 256>>>(knn1, knn2);
  k_xyz<<<dim3(16, 2, 2), 256>>>(pc1, pc2);
  k_knn_cos<<<dim3(64, 2, 2), 256, 84992>>>();
  k_euclid<<<dim3(64, 2, 2), 256>>>();
  k_mlp<<<dim3(512, 2, 2), 256, 110592>>>(Wpos, bpos, Wm1, bm1, Wm2, bm2, out);
}

// round 9
// speedup vs baseline: 1.1382x; 1.1382x over previous
#include <cuda_runtime.h>
#include <math.h>
#include <float.h>

#define BB 2
#define NN 4096
#define CC 64
#define BN (BB*NN)

typedef unsigned long long u64;

// ---------------- device scratch (no allocations allowed) ----------------
__device__ float g_f1a[BN*CC];       // point-major [b*N+n][d]
__device__ float g_f2a[BN*CC];
__device__ float g_f2b[BN*CC];
__device__ float g_f1b[BN*CC];
__device__ float g_kn[2][CC*BN];     // channel-major [s][(b*64+c)*NN + n]
__device__ float4 g_xyz[2][BN];      // (x,y,z,|p|^2)
__device__ int   g_idx[2*BN*16];     // [dir][b][n][16]: 0..7 cosine, 8..15 euclid

__device__ __forceinline__ float leaky(float x){ return fmaxf(x, 0.1f*x); }

// ---- packed fp32x2 helpers (used in k_mlp only, measured neutral-positive)
__device__ __forceinline__ u64 pk2(float lo, float hi){
  u64 r; asm("mov.b64 %0, {%1, %2};" : "=l"(r) : "f"(lo), "f"(hi)); return r;
}
__device__ __forceinline__ void fma2(u64 &d, u64 a, u64 b){
  asm("fma.rn.f32x2 %0, %1, %2, %0;" : "+l"(d) : "l"(a), "l"(b));
}
__device__ __forceinline__ float2 up2(u64 v){
  float2 r; asm("mov.b64 {%0, %1}, %2;" : "=f"(r.x), "=f"(r.y) : "l"(v)); return r;
}

#define INSERT8(dA, iA, dval, mval)                                         \
  if ((dval) < dA[7]) {                                                     \
    dA[7] = (dval); iA[7] = (mval);                                         \
    _Pragma("unroll")                                                       \
    for (int _i = 7; _i > 0; _i--) {                                        \
      if (dA[_i] < dA[_i-1]) {                                              \
        float _tv = dA[_i]; dA[_i] = dA[_i-1]; dA[_i-1] = _tv;              \
        int   _ti = iA[_i]; iA[_i] = iA[_i-1]; iA[_i-1] = _ti;              \
      }                                                                     \
    }                                                                       \
  }

// ---------------- 1x1 conv transforms: f1a,f2a,f2b,f1b -------------------
__global__ __launch_bounds__(256) void k_transform(
    const float* __restrict__ feat1, const float* __restrict__ feat2,
    const float* __restrict__ W11, const float* __restrict__ b11,
    const float* __restrict__ W22, const float* __restrict__ b22)
{
  int n0 = blockIdx.x * 64, b = blockIdx.y, combo = blockIdx.z;
  const float* src  = (combo == 0 || combo == 3) ? feat1 : feat2;
  const float* W    = (combo == 0 || combo == 2) ? W11 : W22;
  const float* bias = (combo == 0 || combo == 2) ? b11 : b22;
  float* dst = (combo == 0) ? g_f1a : (combo == 1) ? g_f2a : (combo == 2) ? g_f2b : g_f1b;

  __shared__ float sF[64*65];   // [c][nn]
  __shared__ float sWT[64*65];  // [c][d]
  __shared__ float sB[64];
  int t = threadIdx.x;

  #pragma unroll
  for (int i = 0; i < 16; i++) {
    int idx = t + i*256;
    int hi = idx >> 6, lo = idx & 63;
    sF[hi*65 + lo]  = src[(b*64 + hi)*NN + n0 + lo];
    sWT[lo*65 + hi] = W[hi*64 + lo];
  }
  if (t < 64) sB[t] = bias[t];
  __syncthreads();

  int d = t & 63, g = t >> 6;
  for (int i = 0; i < 16; i++) {
    int nn = g*16 + i;
    float acc = sB[d];
    #pragma unroll
    for (int c = 0; c < 64; c++) acc += sWT[c*65 + d] * sF[c*65 + nn];
    dst[(b*NN + n0 + nn)*64 + d] = acc;
  }
}

// ------- normalize knn features (stay channel-major, just scale) ----------
__global__ __launch_bounds__(256) void k_normalize(
    const float* __restrict__ knn1, const float* __restrict__ knn2)
{
  int n0 = blockIdx.x * 64, b = blockIdx.y, s = blockIdx.z;
  const float* src = s ? knn2 : knn1;
  __shared__ float sF[64*65];
  __shared__ float sInv[64];
  int t = threadIdx.x;

  #pragma unroll
  for (int i = 0; i < 16; i++) {
    int idx = t + i*256;
    int c = idx >> 6, x = idx & 63;
    sF[c*65 + x] = src[(b*64 + c)*NN + n0 + x];
  }
  __syncthreads();
  if (t < 64) {
    float sum = 0.f;
    #pragma unroll
    for (int c = 0; c < 64; c++) { float v = sF[c*65 + t]; sum += v*v; }
    sInv[t] = 1.0f / sqrtf(sum + 1e-8f);
  }
  __syncthreads();
  #pragma unroll
  for (int i = 0; i < 16; i++) {
    int idx = t + i*256;
    int c = idx >> 6, x = idx & 63;
    g_kn[s][(b*64 + c)*NN + n0 + x] = sF[c*65 + x] * sInv[x];
  }
}

// ---------------- xyz transpose + squared norms ---------------------------
__global__ __launch_bounds__(256) void k_xyz(
    const float* __restrict__ pc1, const float* __restrict__ pc2)
{
  int b = blockIdx.y, s = blockIdx.z;
  const float* pc = s ? pc2 : pc1;
  int n = blockIdx.x*256 + threadIdx.x;
  float x = pc[(b*3 + 0)*NN + n];
  float y = pc[(b*3 + 1)*NN + n];
  float z = pc[(b*3 + 2)*NN + n];
  g_xyz[s][b*NN + n] = make_float4(x, y, z, x*x + y*y + z*z);
}

// --------- cosine KNN: 64q x 128m tile, scalar outer-product + scan -------
// Per thread: 4 queries x 8 candidates (m at tm*4 and tm*4+64 -> conflict-free).
// smem (floats): sQ[64c][68] 4352 | sD[64c][132] 8448 | dist[64q][132] 8448
//   total 21248 floats = 84992 B
__global__ __launch_bounds__(256, 2) void k_knn_cos()
{
  extern __shared__ float smem[];
  float* sQ   = smem;
  float* sD   = smem + 4352;
  float* dist = smem + 12800;

  int dir = blockIdx.z, b = blockIdx.y;
  int qbase = blockIdx.x * 64;
  const float* Qg = dir ? g_kn[1] : g_kn[0];
  const float* Dg = dir ? g_kn[0] : g_kn[1];

  int t = threadIdx.x;
  int tq = t >> 4, tm = t & 15;   // GEMM: 4 queries x 8 candidates per thread
  int sq = t >> 2, sl = t & 3;    // scan: 4 threads per query

  // fill sQ [c][q]
  {
    int c0 = t >> 4, m4 = t & 15;
    #pragma unroll
    for (int i = 0; i < 4; i++) {
      int c = c0 + 16*i;
      *(float4*)&sQ[c*68 + m4*4] =
        *(const float4*)&Qg[(b*64 + c)*NN + qbase + m4*4];
    }
  }

  float dC[8]; int iC[8];
  #pragma unroll
  for (int i = 0; i < 8; i++) { dC[i] = FLT_MAX; iC[i] = -1; }

  for (int mb = 0; mb < NN; mb += 128) {
    __syncthreads();
    // fill sD [c][m] : 64 rows x 128 floats (conflict-free, 16B lane stride)
    {
      int c0 = t >> 5, c4 = t & 31;
      #pragma unroll
      for (int i = 0; i < 8; i++) {
        int c = c0 + 8*i;
        *(float4*)&sD[c*132 + c4*4] =
          *(const float4*)&Dg[(b*64 + c)*NN + mb + c4*4];
      }
    }
    __syncthreads();

    // scalar outer product: q-frag float4 (broadcast), m-frags at tm*4 / tm*4+64
    float a0[4][4], a1[4][4];
    #pragma unroll
    for (int i = 0; i < 4; i++)
      #pragma unroll
      for (int j = 0; j < 4; j++) { a0[i][j] = 0.f; a1[i][j] = 0.f; }

    #pragma unroll 4
    for (int c = 0; c < 64; c++) {
      float4 qf = *(const float4*)&sQ[c*68 + tq*4];
      float4 m0 = *(const float4*)&sD[c*132 + tm*4];
      float4 m1 = *(const float4*)&sD[c*132 + 64 + tm*4];
      float qv[4] = {qf.x, qf.y, qf.z, qf.w};
      float m0v[4] = {m0.x, m0.y, m0.z, m0.w};
      float m1v[4] = {m1.x, m1.y, m1.z, m1.w};
      #pragma unroll
      for (int i = 0; i < 4; i++)
        #pragma unroll
        for (int j = 0; j < 4; j++) {
          a0[i][j] += qv[i]*m0v[j];
          a1[i][j] += qv[i]*m1v[j];
        }
    }

    // dist = 1 - dot  (STS.128 at tm*4 / tm*4+64: conflict-free)
    #pragma unroll
    for (int qi = 0; qi < 4; qi++) {
      int ro = (tq*4 + qi)*132;
      *(float4*)&dist[ro + tm*4] =
        make_float4(1.f-a0[qi][0], 1.f-a0[qi][1], 1.f-a0[qi][2], 1.f-a0[qi][3]);
      *(float4*)&dist[ro + 64 + tm*4] =
        make_float4(1.f-a1[qi][0], 1.f-a1[qi][1], 1.f-a1[qi][2], 1.f-a1[qi][3]);
    }
    __syncthreads();

    // scan: thread (sq, sl) handles candidates sl*32 .. sl*32+31 (ascending)
    #pragma unroll
    for (int i4 = 0; i4 < 8; i4++) {
      float4 dv = *(const float4*)&dist[sq*132 + sl*32 + i4*4];
      int m0 = mb + sl*32 + i4*4;
      INSERT8(dC, iC, dv.x, m0+0);
      INSERT8(dC, iC, dv.y, m0+1);
      INSERT8(dC, iC, dv.z, m0+2);
      INSERT8(dC, iC, dv.w, m0+3);
    }
  }

  // final merge: 4 sorted runs of 8 per query -> top-8
  __syncthreads();
  float* mD = dist;
  int*   mI = (int*)(dist + 2048);
  #pragma unroll
  for (int i = 0; i < 8; i++) {
    mD[(sq*4 + sl)*8 + i] = dC[i];
    mI[(sq*4 + sl)*8 + i] = iC[i];
  }
  __syncthreads();
  if (t < 64) {
    int base = t*32;
    int gb = ((dir*BB + b)*NN + qbase + t)*16;
    for (int r = 0; r < 8; r++) {
      float bd = FLT_MAX; int bs = 0;
      #pragma unroll
      for (int s2 = 0; s2 < 32; s2++) {
        float v = mD[base + s2];
        if (v < bd) { bd = v; bs = s2; }
      }
      g_idx[gb + r] = mI[base + bs];
      mD[base + bs] = FLT_MAX;
    }
  }
}

// --------- euclid KNN: 4 threads/query, blocked ranges, smem merge --------
__global__ __launch_bounds__(256) void k_euclid()
{
  int dir = blockIdx.z, b = blockIdx.y;
  int qbase = blockIdx.x * 64;
  const float4* Qx = dir ? g_xyz[1] : g_xyz[0];
  const float4* Dx = dir ? g_xyz[0] : g_xyz[1];
  int t = threadIdx.x;
  int ql = t >> 2, sl = t & 3;
  int q = qbase + ql;

  float4 qx = Qx[b*NN + q];
  float dE[8]; int iE[8];
  #pragma unroll
  for (int i = 0; i < 8; i++) { dE[i] = FLT_MAX; iE[i] = -1; }

  const float4* base = &Dx[b*NN + sl*1024];
  #pragma unroll 4
  for (int i = 0; i < 1024; i++) {
    float4 d = __ldg(&base[i]);
    float de = qx.w + d.w - 2.0f*(qx.x*d.x + qx.y*d.y + qx.z*d.z);
    INSERT8(dE, iE, de, sl*1024 + i);
  }

  __shared__ float mD[2048];
  __shared__ int   mI[2048];
  #pragma unroll
  for (int i = 0; i < 8; i++) { mD[t*8 + i] = dE[i]; mI[t*8 + i] = iE[i]; }
  __syncthreads();
  if (t < 64) {
    int mb = t*32;
    int gb = ((dir*BB + b)*NN + qbase + t)*16 + 8;
    for (int r = 0; r < 8; r++) {
      float bd = FLT_MAX; int bs = 0;
      #pragma unroll
      for (int s2 = 0; s2 < 32; s2++) {
        float v = mD[mb + s2];
        if (v < bd) { bd = v; bs = s2; }
      }
      g_idx[gb + r] = mI[mb + bs];
      mD[mb + bs] = FLT_MAX;
    }
  }
}

// ------ gather + pos-MLP + 2x MLP (FFMA2 register-blocked) + maxpool ------
// 8 queries/block -> 128 rows, column-major buffers, row stride 136.
// smem (floats): sW1 4352 | sW2 4352 | bufA 8704 | bufB 8704 | sP1 512
//   | sPos 256 | sB1 64 | sB2 64 | sDir 512 | sNb 128 = 27648 (110592 B)
__global__ __launch_bounds__(256, 2) void k_mlp(
    const float* __restrict__ Wpos, const float* __restrict__ bpos,
    const float* __restrict__ Wm1,  const float* __restrict__ b1,
    const float* __restrict__ Wm2,  const float* __restrict__ b2,
    float* __restrict__ out)
{
  extern __shared__ float sm[];
  float* sW1  = sm;
  float* sW2  = sm + 4352;
  float* bufA = sm + 8704;
  float* bufB = sm + 17408;
  float* sP1  = sm + 26112;
  float4* sPos = (float4*)(sm + 26624);
  float* sB1  = sm + 26880;
  float* sB2  = sm + 26944;
  float4* sDir = (float4*)(sm + 27008);
  int*   sNb  = (int*)(sm + 27520);

  int dir = blockIdx.z, b = blockIdx.y;
  int n0 = blockIdx.x * 8;
  const float* p1 = dir ? g_f2b : g_f1a;
  const float* p2 = dir ? g_f1b : g_f2a;
  const float4* Qx = dir ? g_xyz[1] : g_xyz[0];
  const float4* Dx = dir ? g_xyz[0] : g_xyz[1];

  int t = threadIdx.x;

  // load both weights transposed: sW[c*68+e] = W[e*64+c]
  #pragma unroll
  for (int i = 0; i < 16; i++) {
    int idx = t + i*256;
    int e = idx >> 6, c = idx & 63;
    sW1[c*68 + e] = Wm1[idx];
    sW2[c*68 + e] = Wm2[idx];
  }
  if (t < 64) {
    sPos[t] = make_float4(Wpos[t*3], Wpos[t*3+1], Wpos[t*3+2], bpos[t]);
    sB1[t] = b1[t];
    sB2[t] = b2[t];
  }
  #pragma unroll
  for (int i = 0; i < 2; i++) {
    int idx = t + i*256;
    int q = idx >> 6, d = idx & 63;
    sP1[idx] = p1[(b*NN + n0 + q)*64 + d];
  }
  if (t < 128) {
    int q = t >> 4, k = t & 15;
    int nb = g_idx[((dir*BB + b)*NN + n0 + q)*16 + k];
    sNb[t] = nb;
    float4 dxv = Dx[b*NN + nb], qxv = Qx[b*NN + n0 + q];
    sDir[t] = make_float4(dxv.x - qxv.x, dxv.y - qxv.y, dxv.z - qxv.z, 0.f);
  }
  __syncthreads();

  // stage 0: bufA[d][row] = leaky(g2 + p1 + pos)
  {
    int row = t & 127, half = t >> 7;
    int nb = sNb[row];
    int q = row >> 4;
    float4 dv = sDir[row];
    const float4* p2row = (const float4*)&p2[(b*NN + nb)*64] + half*8;
    const float* p1row = &sP1[q*64 + half*32];
    #pragma unroll
    for (int j = 0; j < 8; j++) {
      int d = half*32 + j*4;
      float4 g = p2row[j];
      float4 w0 = sPos[d+0], w1 = sPos[d+1], w2 = sPos[d+2], w3 = sPos[d+3];
      float v0 = g.x + p1row[j*4+0] + (dv.x*w0.x + dv.y*w0.y + dv.z*w0.z + w0.w);
      float v1 = g.y + p1row[j*4+1] + (dv.x*w1.x + dv.y*w1.y + dv.z*w1.z + w1.w);
      float v2 = g.z + p1row[j*4+2] + (dv.x*w2.x + dv.y*w2.y + dv.z*w2.z + w2.w);
      float v3 = g.w + p1row[j*4+3] + (dv.x*w3.x + dv.y*w3.y + dv.z*w3.z + w3.w);
      bufA[(d+0)*136 + row] = leaky(v0);
      bufA[(d+1)*136 + row] = leaky(v1);
      bufA[(d+2)*136 + row] = leaky(v2);
      bufA[(d+3)*136 + row] = leaky(v3);
    }
  }
  __syncthreads();

  int rq = t >> 4, tm = t & 15;
  int r0 = rq*8, e0 = tm*4;

  // stage 1: bufB[e][row] = leaky(sum_c bufA[c][row]*W1[e][c] + b1)
  {
    u64 acc[4][4];
    #pragma unroll
    for (int i = 0; i < 4; i++)
      #pragma unroll
      for (int j = 0; j < 4; j++) acc[i][j] = 0ULL;
    #pragma unroll 4
    for (int c = 0; c < 64; c++) {
      float4 wf = *(const float4*)&sW1[c*68 + e0];
      ulonglong2 ra = *(const ulonglong2*)&bufA[c*136 + r0];
      ulonglong2 rb = *(const ulonglong2*)&bufA[c*136 + r0 + 4];
      u64 w0 = pk2(wf.x, wf.x), w1 = pk2(wf.y, wf.y);
      u64 w2 = pk2(wf.z, wf.z), w3 = pk2(wf.w, wf.w);
      fma2(acc[0][0], ra.x, w0); fma2(acc[0][1], ra.x, w1);
      fma2(acc[0][2], ra.x, w2); fma2(acc[0][3], ra.x, w3);
      fma2(acc[1][0], ra.y, w0); fma2(acc[1][1], ra.y, w1);
      fma2(acc[1][2], ra.y, w2); fma2(acc[1][3], ra.y, w3);
      fma2(acc[2][0], rb.x, w0); fma2(acc[2][1], rb.x, w1);
      fma2(acc[2][2], rb.x, w2); fma2(acc[2][3], rb.x, w3);
      fma2(acc[3][0], rb.y, w0); fma2(acc[3][1], rb.y, w1);
      fma2(acc[3][2], rb.y, w2); fma2(acc[3][3], rb.y, w3);
    }
    #pragma unroll
    for (int j = 0; j < 4; j++) {
      float bb = sB1[e0 + j];
      float2 v01 = up2(acc[0][j]), v23 = up2(acc[1][j]);
      float2 v45 = up2(acc[2][j]), v67 = up2(acc[3][j]);
      float4 lo = make_float4(leaky(v01.x+bb), leaky(v01.y+bb),
                              leaky(v23.x+bb), leaky(v23.y+bb));
      float4 hi = make_float4(leaky(v45.x+bb), leaky(v45.y+bb),
                              leaky(v67.x+bb), leaky(v67.y+bb));
      *(float4*)&bufB[(e0+j)*136 + r0]     = lo;
      *(float4*)&bufB[(e0+j)*136 + r0 + 4] = hi;
    }
  }
  __syncthreads();

  // stage 2: bufA[e][row] = leaky(sum_c bufB[c][row]*W2[e][c] + b2)
  {
    u64 acc[4][4];
    #pragma unroll
    for (int i = 0; i < 4; i++)
      #pragma unroll
      for (int j = 0; j < 4; j++) acc[i][j] = 0ULL;
    #pragma unroll 4
    for (int c = 0; c < 64; c++) {
      float4 wf = *(const float4*)&sW2[c*68 + e0];
      ulonglong2 ra = *(const ulonglong2*)&bufB[c*136 + r0];
      ulonglong2 rb = *(const ulonglong2*)&bufB[c*136 + r0 + 4];
      u64 w0 = pk2(wf.x, wf.x), w1 = pk2(wf.y, wf.y);
      u64 w2 = pk2(wf.z, wf.z), w3 = pk2(wf.w, wf.w);
      fma2(acc[0][0], ra.x, w0); fma2(acc[0][1], ra.x, w1);
      fma2(acc[0][2], ra.x, w2); fma2(acc[0][3], ra.x, w3);
      fma2(acc[1][0], ra.y, w0); fma2(acc[1][1], ra.y, w1);
      fma2(acc[1][2], ra.y, w2); fma2(acc[1][3], ra.y, w3);
      fma2(acc[2][0], rb.x, w0); fma2(acc[2][1], rb.x, w1);
      fma2(acc[2][2], rb.x, w2); fma2(acc[2][3], rb.x, w3);
      fma2(acc[3][0], rb.y, w0); fma2(acc[3][1], rb.y, w1);
      fma2(acc[3][2], rb.y, w2); fma2(acc[3][3], rb.y, w3);
    }
    #pragma unroll
    for (int j = 0; j < 4; j++) {
      float bb = sB2[e0 + j];
      float2 v01 = up2(acc[0][j]), v23 = up2(acc[1][j]);
      float2 v45 = up2(acc[2][j]), v67 = up2(acc[3][j]);
      float4 lo = make_float4(leaky(v01.x+bb), leaky(v01.y+bb),
                              leaky(v23.x+bb), leaky(v23.y+bb));
      float4 hi = make_float4(leaky(v45.x+bb), leaky(v45.y+bb),
                              leaky(v67.x+bb), leaky(v67.y+bb));
      *(float4*)&bufA[(e0+j)*136 + r0]     = lo;
      *(float4*)&bufA[(e0+j)*136 + r0 + 4] = hi;
    }
  }
  __syncthreads();

  // maxpool over k (16 contiguous rows per query) + store [e][n]
  #pragma unroll
  for (int i = 0; i < 2; i++) {
    int o = t + i*256;
    int q = o & 7, e = o >> 3;
    const float4* r = (const float4*)&bufA[e*136 + q*16];
    float4 v0 = r[0], v1 = r[1], v2 = r[2], v3 = r[3];
    float m = fmaxf(fmaxf(fmaxf(v0.x, v0.y), fmaxf(v0.z, v0.w)),
                    fmaxf(fmaxf(v1.x, v1.y), fmaxf(v1.z, v1.w)));
    m = fmaxf(m, fmaxf(fmaxf(fmaxf(v2.x, v2.y), fmaxf(v2.z, v2.w)),
                       fmaxf(fmaxf(v3.x, v3.y), fmaxf(v3.z, v3.w))));
    out[dir*(BB*64*NN) + b*(64*NN) + e*NN + (n0 + q)] = m;
  }
}

// ---------------- launch ---------------------------------------------------
extern "C" void kernel_launch(void* const* d_in, const int* in_sizes, int n_in,
                              void* d_out, int out_size)
{
  const float* pc1   = (const float*)d_in[0];
  const float* pc2   = (const float*)d_in[1];
  const float* feat1 = (const float*)d_in[2];
  const float* feat2 = (const float*)d_in[3];
  const float* knn1  = (const float*)d_in[4];
  const float* knn2  = (const float*)d_in[5];
  const float* W11   = (const float*)d_in[6];
  const float* b11   = (const float*)d_in[7];
  const float* W22   = (const float*)d_in[8];
  const float* b22   = (const float*)d_in[9];
  const float* Wpos  = (const float*)d_in[10];
  const float* bpos  = (const float*)d_in[11];
  const float* Wm1   = (const float*)d_in[12];
  const float* bm1   = (const float*)d_in[13];
  const float* Wm2   = (const float*)d_in[14];
  const float* bm2   = (const float*)d_in[15];
  float* out = (float*)d_out;

  cudaFuncSetAttribute(k_knn_cos, cudaFuncAttributeMaxDynamicSharedMemorySize, 84992);
  cudaFuncSetAttribute(k_mlp, cudaFuncAttributeMaxDynamicSharedMemorySize, 110592);

  k_transform<<<dim3(64, 2, 4), 256>>>(feat1, feat2, W11, b11, W22, b22);
  k_normalize<<<dim3(64, 2, 2), 256>>>(knn1, knn2);
  k_xyz<<<dim3(16, 2, 2), 256>>>(pc1, pc2);
  k_knn_cos<<<dim3(64, 2, 2), 256, 84992>>>();
  k_euclid<<<dim3(64, 2, 2), 256>>>();
  k_mlp<<<dim3(512, 2, 2), 256, 110592>>>(Wpos, bpos, Wm1, bm1, Wm2, bm2, out);
}

// round 12
// speedup vs baseline: 1.1786x; 1.0356x over previous
#include <cuda_runtime.h>
#include <math.h>
#include <float.h>

#define BB 2
#define NN 4096
#define CC 64
#define BN (BB*NN)

typedef unsigned long long u64;

// ---------------- device scratch (no allocations allowed) ----------------
__device__ float g_f1a[BN*CC];       // point-major [b*N+n][d]
__device__ float g_f2a[BN*CC];
__device__ float g_f2b[BN*CC];
__device__ float g_f1b[BN*CC];
__device__ float g_kn[2][CC*BN];     // channel-major [s][(b*64+c)*NN + n]
__device__ float4 g_xyz[2][BN];      // (x,y,z,|p|^2)
__device__ int   g_idx[2*BN*16];     // [dir][b][n][16]: 0..7 cosine, 8..15 euclid

__device__ __forceinline__ float leaky(float x){ return fmaxf(x, 0.1f*x); }

// ---- packed fp32x2 helpers ----
__device__ __forceinline__ u64 pk2(float lo, float hi){
  u64 r; asm("mov.b64 %0, {%1, %2};" : "=l"(r) : "f"(lo), "f"(hi)); return r;
}
__device__ __forceinline__ void fma2(u64 &d, u64 a, u64 b){
  asm("fma.rn.f32x2 %0, %1, %2, %0;" : "+l"(d) : "l"(a), "l"(b));
}
__device__ __forceinline__ float2 up2(u64 v){
  float2 r; asm("mov.b64 {%0, %1}, %2;" : "=f"(r.x), "=f"(r.y) : "l"(v)); return r;
}

#define INSERT8(dA, iA, dval, mval)                                         \
  if ((dval) < dA[7]) {                                                     \
    dA[7] = (dval); iA[7] = (mval);                                         \
    _Pragma("unroll")                                                       \
    for (int _i = 7; _i > 0; _i--) {                                        \
      if (dA[_i] < dA[_i-1]) {                                              \
        float _tv = dA[_i]; dA[_i] = dA[_i-1]; dA[_i-1] = _tv;              \
        int   _ti = iA[_i]; iA[_i] = iA[_i-1]; iA[_i-1] = _ti;              \
      }                                                                     \
    }                                                                       \
  }

// ---------------- 1x1 conv transforms: f1a,f2a,f2b,f1b -------------------
__global__ __launch_bounds__(256) void k_transform(
    const float* __restrict__ feat1, const float* __restrict__ feat2,
    const float* __restrict__ W11, const float* __restrict__ b11,
    const float* __restrict__ W22, const float* __restrict__ b22)
{
  int n0 = blockIdx.x * 64, b = blockIdx.y, combo = blockIdx.z;
  const float* src  = (combo == 0 || combo == 3) ? feat1 : feat2;
  const float* W    = (combo == 0 || combo == 2) ? W11 : W22;
  const float* bias = (combo == 0 || combo == 2) ? b11 : b22;
  float* dst = (combo == 0) ? g_f1a : (combo == 1) ? g_f2a : (combo == 2) ? g_f2b : g_f1b;

  __shared__ float sF[64*65];   // [c][nn]
  __shared__ float sWT[64*65];  // [c][d]
  __shared__ float sB[64];
  int t = threadIdx.x;

  #pragma unroll
  for (int i = 0; i < 16; i++) {
    int idx = t + i*256;
    int hi = idx >> 6, lo = idx & 63;
    sF[hi*65 + lo]  = src[(b*64 + hi)*NN + n0 + lo];
    sWT[lo*65 + hi] = W[hi*64 + lo];
  }
  if (t < 64) sB[t] = bias[t];
  __syncthreads();

  int d = t & 63, g = t >> 6;
  for (int i = 0; i < 16; i++) {
    int nn = g*16 + i;
    float acc = sB[d];
    #pragma unroll
    for (int c = 0; c < 64; c++) acc += sWT[c*65 + d] * sF[c*65 + nn];
    dst[(b*NN + n0 + nn)*64 + d] = acc;
  }
}

// ------- normalize knn features (stay channel-major, just scale) ----------
__global__ __launch_bounds__(256) void k_normalize(
    const float* __restrict__ knn1, const float* __restrict__ knn2)
{
  int n0 = blockIdx.x * 64, b = blockIdx.y, s = blockIdx.z;
  const float* src = s ? knn2 : knn1;
  __shared__ float sF[64*65];
  __shared__ float sInv[64];
  int t = threadIdx.x;

  #pragma unroll
  for (int i = 0; i < 16; i++) {
    int idx = t + i*256;
    int c = idx >> 6, x = idx & 63;
    sF[c*65 + x] = src[(b*64 + c)*NN + n0 + x];
  }
  __syncthreads();
  if (t < 64) {
    float sum = 0.f;
    #pragma unroll
    for (int c = 0; c < 64; c++) { float v = sF[c*65 + t]; sum += v*v; }
    sInv[t] = 1.0f / sqrtf(sum + 1e-8f);
  }
  __syncthreads();
  #pragma unroll
  for (int i = 0; i < 16; i++) {
    int idx = t + i*256;
    int c = idx >> 6, x = idx & 63;
    g_kn[s][(b*64 + c)*NN + n0 + x] = sF[c*65 + x] * sInv[x];
  }
}

// ---------------- xyz transpose + squared norms ---------------------------
__global__ __launch_bounds__(256) void k_xyz(
    const float* __restrict__ pc1, const float* __restrict__ pc2)
{
  int b = blockIdx.y, s = blockIdx.z;
  const float* pc = s ? pc2 : pc1;
  int n = blockIdx.x*256 + threadIdx.x;
  float x = pc[(b*3 + 0)*NN + n];
  float y = pc[(b*3 + 1)*NN + n];
  float z = pc[(b*3 + 2)*NN + n];
  g_xyz[s][b*NN + n] = make_float4(x, y, z, x*x + y*y + z*z);
}

// --------- cosine KNN: 64q x 128m tile, scalar outer-product + scan -------
// (unchanged from R9 — measured 315us, near scalar ceiling)
__global__ __launch_bounds__(256, 2) void k_knn_cos()
{
  extern __shared__ float smem[];
  float* sQ   = smem;
  float* sD   = smem + 4352;
  float* dist = smem + 12800;

  int dir = blockIdx.z, b = blockIdx.y;
  int qbase = blockIdx.x * 64;
  const float* Qg = dir ? g_kn[1] : g_kn[0];
  const float* Dg = dir ? g_kn[0] : g_kn[1];

  int t = threadIdx.x;
  int tq = t >> 4, tm = t & 15;
  int sq = t >> 2, sl = t & 3;

  {
    int c0 = t >> 4, m4 = t & 15;
    #pragma unroll
    for (int i = 0; i < 4; i++) {
      int c = c0 + 16*i;
      *(float4*)&sQ[c*68 + m4*4] =
        *(const float4*)&Qg[(b*64 + c)*NN + qbase + m4*4];
    }
  }

  float dC[8]; int iC[8];
  #pragma unroll
  for (int i = 0; i < 8; i++) { dC[i] = FLT_MAX; iC[i] = -1; }

  for (int mb = 0; mb < NN; mb += 128) {
    __syncthreads();
    {
      int c0 = t >> 5, c4 = t & 31;
      #pragma unroll
      for (int i = 0; i < 8; i++) {
        int c = c0 + 8*i;
        *(float4*)&sD[c*132 + c4*4] =
          *(const float4*)&Dg[(b*64 + c)*NN + mb + c4*4];
      }
    }
    __syncthreads();

    float a0[4][4], a1[4][4];
    #pragma unroll
    for (int i = 0; i < 4; i++)
      #pragma unroll
      for (int j = 0; j < 4; j++) { a0[i][j] = 0.f; a1[i][j] = 0.f; }

    #pragma unroll 4
    for (int c = 0; c < 64; c++) {
      float4 qf = *(const float4*)&sQ[c*68 + tq*4];
      float4 m0 = *(const float4*)&sD[c*132 + tm*4];
      float4 m1 = *(const float4*)&sD[c*132 + 64 + tm*4];
      float qv[4] = {qf.x, qf.y, qf.z, qf.w};
      float m0v[4] = {m0.x, m0.y, m0.z, m0.w};
      float m1v[4] = {m1.x, m1.y, m1.z, m1.w};
      #pragma unroll
      for (int i = 0; i < 4; i++)
        #pragma unroll
        for (int j = 0; j < 4; j++) {
          a0[i][j] += qv[i]*m0v[j];
          a1[i][j] += qv[i]*m1v[j];
        }
    }

    #pragma unroll
    for (int qi = 0; qi < 4; qi++) {
      int ro = (tq*4 + qi)*132;
      *(float4*)&dist[ro + tm*4] =
        make_float4(1.f-a0[qi][0], 1.f-a0[qi][1], 1.f-a0[qi][2], 1.f-a0[qi][3]);
      *(float4*)&dist[ro + 64 + tm*4] =
        make_float4(1.f-a1[qi][0], 1.f-a1[qi][1], 1.f-a1[qi][2], 1.f-a1[qi][3]);
    }
    __syncthreads();

    #pragma unroll
    for (int i4 = 0; i4 < 8; i4++) {
      float4 dv = *(const float4*)&dist[sq*132 + sl*32 + i4*4];
      int m0 = mb + sl*32 + i4*4;
      INSERT8(dC, iC, dv.x, m0+0);
      INSERT8(dC, iC, dv.y, m0+1);
      INSERT8(dC, iC, dv.z, m0+2);
      INSERT8(dC, iC, dv.w, m0+3);
    }
  }

  __syncthreads();
  float* mD = dist;
  int*   mI = (int*)(dist + 2048);
  #pragma unroll
  for (int i = 0; i < 8; i++) {
    mD[(sq*4 + sl)*8 + i] = dC[i];
    mI[(sq*4 + sl)*8 + i] = iC[i];
  }
  __syncthreads();
  if (t < 64) {
    int base = t*32;
    int gb = ((dir*BB + b)*NN + qbase + t)*16;
    for (int r = 0; r < 8; r++) {
      float bd = FLT_MAX; int bs = 0;
      #pragma unroll
      for (int s2 = 0; s2 < 32; s2++) {
        float v = mD[base + s2];
        if (v < bd) { bd = v; bs = s2; }
      }
      g_idx[gb + r] = mI[base + bs];
      mD[base + bs] = FLT_MAX;
    }
  }
}

// --------- euclid KNN: 4 threads/query, blocked ranges, smem merge --------
__global__ __launch_bounds__(256) void k_euclid()
{
  int dir = blockIdx.z, b = blockIdx.y;
  int qbase = blockIdx.x * 64;
  const float4* Qx = dir ? g_xyz[1] : g_xyz[0];
  const float4* Dx = dir ? g_xyz[0] : g_xyz[1];
  int t = threadIdx.x;
  int ql = t >> 2, sl = t & 3;
  int q = qbase + ql;

  float4 qx = Qx[b*NN + q];
  float dE[8]; int iE[8];
  #pragma unroll
  for (int i = 0; i < 8; i++) { dE[i] = FLT_MAX; iE[i] = -1; }

  const float4* base = &Dx[b*NN + sl*1024];
  #pragma unroll 4
  for (int i = 0; i < 1024; i++) {
    float4 d = __ldg(&base[i]);
    float de = qx.w + d.w - 2.0f*(qx.x*d.x + qx.y*d.y + qx.z*d.z);
    INSERT8(dE, iE, de, sl*1024 + i);
  }

  __shared__ float mD[2048];
  __shared__ int   mI[2048];
  #pragma unroll
  for (int i = 0; i < 8; i++) { mD[t*8 + i] = dE[i]; mI[t*8 + i] = iE[i]; }
  __syncthreads();
  if (t < 64) {
    int mb = t*32;
    int gb = ((dir*BB + b)*NN + qbase + t)*16 + 8;
    for (int r = 0; r < 8; r++) {
      float bd = FLT_MAX; int bs = 0;
      #pragma unroll
      for (int s2 = 0; s2 < 32; s2++) {
        float v = mD[mb + s2];
        if (v < bd) { bd = v; bs = s2; }
      }
      g_idx[gb + r] = mI[mb + bs];
      mD[mb + bs] = FLT_MAX;
    }
  }
}

// ------ gather + pos-MLP + 2x MLP + maxpool (conflict-free smem) ----------
// 8 queries/block -> 128 rows, col-major buffers, row stride 132.
// Thread (rq,tm): rows rq*8..+7, e-cols {tm, tm+16, tm+32, tm+48}
//   -> STS.128 bank = 4*tm per phase: conflict-free.
// Stage2 -> registers -> shfl_xor(16) maxpool -> STG (no smem round-trip).
// smem (floats): sW1 4352 | sW2 4352 | bufA 8448 | bufB 8448 | sP1 512
//   | sPos 256 | sB1 64 | sB2 64 | sDir 512 | sNb 128 = 27136 (108544 B)
__global__ __launch_bounds__(256, 2) void k_mlp(
    const float* __restrict__ Wpos, const float* __restrict__ bpos,
    const float* __restrict__ Wm1,  const float* __restrict__ b1,
    const float* __restrict__ Wm2,  const float* __restrict__ b2,
    float* __restrict__ out)
{
  extern __shared__ float sm[];
  float* sW1  = sm;           // [c][68]
  float* sW2  = sm + 4352;
  float* bufA = sm + 8704;    // [d][132], 128 rows used
  float* bufB = sm + 17152;
  float* sP1  = sm + 25600;
  float4* sPos = (float4*)(sm + 26112);
  float* sB1  = sm + 26368;
  float* sB2  = sm + 26432;
  float4* sDir = (float4*)(sm + 26496);
  int*   sNb  = (int*)(sm + 27008);

  int dir = blockIdx.z, b = blockIdx.y;
  int n0 = blockIdx.x * 8;
  const float* p1 = dir ? g_f2b : g_f1a;
  const float* p2 = dir ? g_f1b : g_f2a;
  const float4* Qx = dir ? g_xyz[1] : g_xyz[0];
  const float4* Dx = dir ? g_xyz[0] : g_xyz[1];

  int t = threadIdx.x;

  // load both weights transposed: sW[c*68+e] = W[e*64+c]
  #pragma unroll
  for (int i = 0; i < 16; i++) {
    int idx = t + i*256;
    int e = idx >> 6, c = idx & 63;
    sW1[c*68 + e] = Wm1[idx];
    sW2[c*68 + e] = Wm2[idx];
  }
  if (t < 64) {
    sPos[t] = make_float4(Wpos[t*3], Wpos[t*3+1], Wpos[t*3+2], bpos[t]);
    sB1[t] = b1[t];
    sB2[t] = b2[t];
  }
  #pragma unroll
  for (int i = 0; i < 2; i++) {
    int idx = t + i*256;
    int q = idx >> 6, d = idx & 63;
    sP1[idx] = p1[(b*NN + n0 + q)*64 + d];
  }
  if (t < 128) {
    int q = t >> 4, k = t & 15;
    int nb = g_idx[((dir*BB + b)*NN + n0 + q)*16 + k];
    sNb[t] = nb;
    float4 dxv = Dx[b*NN + nb], qxv = Qx[b*NN + n0 + q];
    sDir[t] = make_float4(dxv.x - qxv.x, dxv.y - qxv.y, dxv.z - qxv.z, 0.f);
  }
  __syncthreads();

  // stage 0: bufA[d][row] = leaky(g2 + p1 + pos)   (scalar STS, row-distinct banks)
  {
    int row = t & 127, half = t >> 7;
    int nb = sNb[row];
    int q = row >> 4;
    float4 dv = sDir[row];
    const float4* p2row = (const float4*)&p2[(b*NN + nb)*64] + half*8;
    const float* p1row = &sP1[q*64 + half*32];
    #pragma unroll
    for (int j = 0; j < 8; j++) {
      int d = half*32 + j*4;
      float4 g = p2row[j];
      float4 w0 = sPos[d+0], w1 = sPos[d+1], w2 = sPos[d+2], w3 = sPos[d+3];
      float v0 = g.x + p1row[j*4+0] + (dv.x*w0.x + dv.y*w0.y + dv.z*w0.z + w0.w);
      float v1 = g.y + p1row[j*4+1] + (dv.x*w1.x + dv.y*w1.y + dv.z*w1.z + w1.w);
      float v2 = g.z + p1row[j*4+2] + (dv.x*w2.x + dv.y*w2.y + dv.z*w2.z + w2.w);
      float v3 = g.w + p1row[j*4+3] + (dv.x*w3.x + dv.y*w3.y + dv.z*w3.z + w3.w);
      bufA[(d+0)*132 + row] = leaky(v0);
      bufA[(d+1)*132 + row] = leaky(v1);
      bufA[(d+2)*132 + row] = leaky(v2);
      bufA[(d+3)*132 + row] = leaky(v3);
    }
  }
  __syncthreads();

  int rq = t >> 4, tm = t & 15;
  int r0 = rq*8;

  // stage 1: bufB[e][row] = leaky(sum_c bufA[c][row]*W1[e][c] + b1), e = tm+16j
  {
    u64 acc[4][4];
    #pragma unroll
    for (int i = 0; i < 4; i++)
      #pragma unroll
      for (int j = 0; j < 4; j++) acc[i][j] = 0ULL;
    #pragma unroll 4
    for (int c = 0; c < 64; c++) {
      float wv0 = sW1[c*68 + tm];
      float wv1 = sW1[c*68 + tm + 16];
      float wv2 = sW1[c*68 + tm + 32];
      float wv3 = sW1[c*68 + tm + 48];
      ulonglong2 ra = *(const ulonglong2*)&bufA[c*132 + r0];
      ulonglong2 rb = *(const ulonglong2*)&bufA[c*132 + r0 + 4];
      u64 w0 = pk2(wv0, wv0), w1 = pk2(wv1, wv1);
      u64 w2 = pk2(wv2, wv2), w3 = pk2(wv3, wv3);
      fma2(acc[0][0], ra.x, w0); fma2(acc[0][1], ra.x, w1);
      fma2(acc[0][2], ra.x, w2); fma2(acc[0][3], ra.x, w3);
      fma2(acc[1][0], ra.y, w0); fma2(acc[1][1], ra.y, w1);
      fma2(acc[1][2], ra.y, w2); fma2(acc[1][3], ra.y, w3);
      fma2(acc[2][0], rb.x, w0); fma2(acc[2][1], rb.x, w1);
      fma2(acc[2][2], rb.x, w2); fma2(acc[2][3], rb.x, w3);
      fma2(acc[3][0], rb.y, w0); fma2(acc[3][1], rb.y, w1);
      fma2(acc[3][2], rb.y, w2); fma2(acc[3][3], rb.y, w3);
    }
    #pragma unroll
    for (int j = 0; j < 4; j++) {
      int e = tm + 16*j;
      float bb = sB1[e];
      float2 v01 = up2(acc[0][j]), v23 = up2(acc[1][j]);
      float2 v45 = up2(acc[2][j]), v67 = up2(acc[3][j]);
      float4 lo = make_float4(leaky(v01.x+bb), leaky(v01.y+bb),
                              leaky(v23.x+bb), leaky(v23.y+bb));
      float4 hi = make_float4(leaky(v45.x+bb), leaky(v45.y+bb),
                              leaky(v67.x+bb), leaky(v67.y+bb));
      *(float4*)&bufB[e*132 + r0]     = lo;
      *(float4*)&bufB[e*132 + r0 + 4] = hi;
    }
  }
  __syncthreads();

  // stage 2: regs -> leaky -> 8-row max -> shfl merge -> STG
  {
    u64 acc[4][4];
    #pragma unroll
    for (int i = 0; i < 4; i++)
      #pragma unroll
      for (int j = 0; j < 4; j++) acc[i][j] = 0ULL;
    #pragma unroll 4
    for (int c = 0; c < 64; c++) {
      float wv0 = sW2[c*68 + tm];
      float wv1 = sW2[c*68 + tm + 16];
      float wv2 = sW2[c*68 + tm + 32];
      float wv3 = sW2[c*68 + tm + 48];
      ulonglong2 ra = *(const ulonglong2*)&bufB[c*132 + r0];
      ulonglong2 rb = *(const ulonglong2*)&bufB[c*132 + r0 + 4];
      u64 w0 = pk2(wv0, wv0), w1 = pk2(wv1, wv1);
      u64 w2 = pk2(wv2, wv2), w3 = pk2(wv3, wv3);
      fma2(acc[0][0], ra.x, w0); fma2(acc[0][1], ra.x, w1);
      fma2(acc[0][2], ra.x, w2); fma2(acc[0][3], ra.x, w3);
      fma2(acc[1][0], ra.y, w0); fma2(acc[1][1], ra.y, w1);
      fma2(acc[1][2], ra.y, w2); fma2(acc[1][3], ra.y, w3);
      fma2(acc[2][0], rb.x, w0); fma2(acc[2][1], rb.x, w1);
      fma2(acc[2][2], rb.x, w2); fma2(acc[2][3], rb.x, w3);
      fma2(acc[3][0], rb.y, w0); fma2(acc[3][1], rb.y, w1);
      fma2(acc[3][2], rb.y, w2); fma2(acc[3][3], rb.y, w3);
    }
    float mj[4];
    #pragma unroll
    for (int j = 0; j < 4; j++) {
      int e = tm + 16*j;
      float bb = sB2[e];
      float2 v01 = up2(acc[0][j]), v23 = up2(acc[1][j]);
      float2 v45 = up2(acc[2][j]), v67 = up2(acc[3][j]);
      float m = fmaxf(fmaxf(leaky(v01.x+bb), leaky(v01.y+bb)),
                      fmaxf(leaky(v23.x+bb), leaky(v23.y+bb)));
      m = fmaxf(m, fmaxf(fmaxf(leaky(v45.x+bb), leaky(v45.y+bb)),
                         fmaxf(leaky(v67.x+bb), leaky(v67.y+bb))));
      mj[j] = m;
    }
    // merge the query's other 8 rows (partner lane: rq^1 -> t^16)
    #pragma unroll
    for (int j = 0; j < 4; j++) {
      float o = __shfl_xor_sync(0xffffffffu, mj[j], 16);
      mj[j] = fmaxf(mj[j], o);
    }
    if ((rq & 1) == 0) {
      int q = rq >> 1;
      long obase = (long)dir*(BB*64*NN) + (long)b*(64*NN) + (n0 + q);
      #pragma unroll
      for (int j = 0; j < 4; j++) {
        int e = tm + 16*j;
        out[obase + (long)e*NN] = mj[j];
      }
    }
  }
}

// ---------------- launch ---------------------------------------------------
extern "C" void kernel_launch(void* const* d_in, const int* in_sizes, int n_in,
                              void* d_out, int out_size)
{
  const float* pc1   = (const float*)d_in[0];
  const float* pc2   = (const float*)d_in[1];
  const float* feat1 = (const float*)d_in[2];
  const float* feat2 = (const float*)d_in[3];
  const float* knn1  = (const float*)d_in[4];
  const float* knn2  = (const float*)d_in[5];
  const float* W11   = (const float*)d_in[6];
  const float* b11   = (const float*)d_in[7];
  const float* W22   = (const float*)d_in[8];
  const float* b22   = (const float*)d_in[9];
  const float* Wpos  = (const float*)d_in[10];
  const float* bpos  = (const float*)d_in[11];
  const float* Wm1   = (const float*)d_in[12];
  const float* bm1   = (const float*)d_in[13];
  const float* Wm2   = (const float*)d_in[14];
  const float* bm2   = (const float*)d_in[15];
  float* out = (float*)d_out;

  cudaFuncSetAttribute(k_knn_cos, cudaFuncAttributeMaxDynamicSharedMemorySize, 84992);
  cudaFuncSetAttribute(k_mlp, cudaFuncAttributeMaxDynamicSharedMemorySize, 108544);

  k_transform<<<dim3(64, 2, 4), 256>>>(feat1, feat2, W11, b11, W22, b22);
  k_normalize<<<dim3(64, 2, 2), 256>>>(knn1, knn2);
  k_xyz<<<dim3(16, 2, 2), 256>>>(pc1, pc2);
  k_knn_cos<<<dim3(64, 2, 2), 256, 84992>>>();
  k_euclid<<<dim3(64, 2, 2), 256>>>();
  k_mlp<<<dim3(512, 2, 2), 256, 108544>>>(Wpos, bpos, Wm1, bm1, Wm2, bm2, out);
}

// round 17
// speedup vs baseline: 1.3530x; 1.1479x over previous
#include <cuda_runtime.h>
#include <cuda_bf16.h>
#include <stdint.h>
#include <math.h>
#include <float.h>

#define BB 2
#define NN 4096
#define CC 64
#define BN (BB*NN)

typedef unsigned long long u64;

// ---------------- device scratch (no allocations allowed) ----------------
__device__ float g_f1a[BN*CC];       // point-major [b*N+n][d]
__device__ float g_f2a[BN*CC];
__device__ float g_f2b[BN*CC];
__device__ float g_f1b[BN*CC];
__device__ float g_knp[2][BN*CC];            // normalized feats fp32 point-major
__device__ __nv_bfloat16 g_kb16[2][BN*CC];   // normalized feats bf16 point-major
__device__ float4 g_xyz[2][BN];      // (x,y,z,|p|^2)
__device__ int   g_idx[2*BN*16];     // [dir][b][n][16]: 0..7 cosine, 8..15 euclid
__device__ int   g_short[2*BN*64];   // cosine shortlist: 8 lanes x top-8 per query

__device__ __forceinline__ float leaky(float x){ return fmaxf(x, 0.1f*x); }

// ---- packed fp32x2 helpers (k_mlp) ----
__device__ __forceinline__ u64 pk2(float lo, float hi){
  u64 r; asm("mov.b64 %0, {%1, %2};" : "=l"(r) : "f"(lo), "f"(hi)); return r;
}
__device__ __forceinline__ void fma2(u64 &d, u64 a, u64 b){
  asm("fma.rn.f32x2 %0, %1, %2, %0;" : "+l"(d) : "l"(a), "l"(b));
}
__device__ __forceinline__ float2 up2(u64 v){
  float2 r; asm("mov.b64 {%0, %1}, %2;" : "=f"(r.x), "=f"(r.y) : "l"(v)); return r;
}

#define INSERT8(dA, iA, dval, mval)                                         \
  if ((dval) < dA[7]) {                                                     \
    dA[7] = (dval); iA[7] = (mval);                                         \
    _Pragma("unroll")                                                       \
    for (int _i = 7; _i > 0; _i--) {                                        \
      if (dA[_i] < dA[_i-1]) {                                              \
        float _tv = dA[_i]; dA[_i] = dA[_i-1]; dA[_i-1] = _tv;              \
        int   _ti = iA[_i]; iA[_i] = iA[_i-1]; iA[_i-1] = _ti;              \
      }                                                                     \
    }                                                                       \
  }

// max-variant: keep 8 LARGEST dots (descending list)
#define INSMAX8(dA, iA, dval, mval)                                         \
  if ((dval) > dA[7]) {                                                     \
    dA[7] = (dval); iA[7] = (mval);                                         \
    _Pragma("unroll")                                                       \
    for (int _i = 7; _i > 0; _i--) {                                        \
      if (dA[_i] > dA[_i-1]) {                                              \
        float _tv = dA[_i]; dA[_i] = dA[_i-1]; dA[_i-1] = _tv;              \
        int   _ti = iA[_i]; iA[_i] = iA[_i-1]; iA[_i-1] = _ti;              \
      }                                                                     \
    }                                                                       \
  }

// ---------------- 1x1 conv transforms: f1a,f2a,f2b,f1b -------------------
__global__ __launch_bounds__(256) void k_transform(
    const float* __restrict__ feat1, const float* __restrict__ feat2,
    const float* __restrict__ W11, const float* __restrict__ b11,
    const float* __restrict__ W22, const float* __restrict__ b22)
{
  int n0 = blockIdx.x * 64, b = blockIdx.y, combo = blockIdx.z;
  const float* src  = (combo == 0 || combo == 3) ? feat1 : feat2;
  const float* W    = (combo == 0 || combo == 2) ? W11 : W22;
  const float* bias = (combo == 0 || combo == 2) ? b11 : b22;
  float* dst = (combo == 0) ? g_f1a : (combo == 1) ? g_f2a : (combo == 2) ? g_f2b : g_f1b;

  __shared__ float sF[64*65];
  __shared__ float sWT[64*65];
  __shared__ float sB[64];
  int t = threadIdx.x;

  #pragma unroll
  for (int i = 0; i < 16; i++) {
    int idx = t + i*256;
    int hi = idx >> 6, lo = idx & 63;
    sF[hi*65 + lo]  = src[(b*64 + hi)*NN + n0 + lo];
    sWT[lo*65 + hi] = W[hi*64 + lo];
  }
  if (t < 64) sB[t] = bias[t];
  __syncthreads();

  int d = t & 63, g = t >> 6;
  for (int i = 0; i < 16; i++) {
    int nn = g*16 + i;
    float acc = sB[d];
    #pragma unroll
    for (int c = 0; c < 64; c++) acc += sWT[c*65 + d] * sF[c*65 + nn];
    dst[(b*NN + n0 + nn)*64 + d] = acc;
  }
}

// ------- normalize knn features -> point-major fp32 + bf16 ----------------
__global__ __launch_bounds__(256) void k_normalize(
    const float* __restrict__ knn1, const float* __restrict__ knn2)
{
  int n0 = blockIdx.x * 64, b = blockIdx.y, s = blockIdx.z;
  const float* src = s ? knn2 : knn1;
  __shared__ float sF[64*65];
  __shared__ float sInv[64];
  int t = threadIdx.x;

  #pragma unroll
  for (int i = 0; i < 16; i++) {
    int idx = t + i*256;
    int c = idx >> 6, x = idx & 63;
    sF[c*65 + x] = src[(b*64 + c)*NN + n0 + x];
  }
  __syncthreads();
  if (t < 64) {
    float sum = 0.f;
    #pragma unroll
    for (int c = 0; c < 64; c++) { float v = sF[c*65 + t]; sum += v*v; }
    sInv[t] = 1.0f / sqrtf(sum + 1e-8f);
  }
  __syncthreads();
  #pragma unroll
  for (int i = 0; i < 16; i++) {
    int idx = t + i*256;
    int c = idx & 63, x = idx >> 6;
    float v = sF[c*65 + x] * sInv[x];
    int o = (b*NN + n0 + x)*64 + c;
    g_knp[s][o]  = v;
    g_kb16[s][o] = __float2bfloat16(v);
  }
}

// ---------------- xyz transpose + squared norms ---------------------------
__global__ __launch_bounds__(256) void k_xyz(
    const float* __restrict__ pc1, const float* __restrict__ pc2)
{
  int b = blockIdx.y, s = blockIdx.z;
  const float* pc = s ? pc2 : pc1;
  int n = blockIdx.x*256 + threadIdx.x;
  float x = pc[(b*3 + 0)*NN + n];
  float y = pc[(b*3 + 1)*NN + n];
  float z = pc[(b*3 + 2)*NN + n];
  g_xyz[s][b*NN + n] = make_float4(x, y, z, x*x + y*y + z*z);
}

// ------ cosine KNN stage 1: bf16 mma.sync -> per-lane approx top-8 --------
// 256 thr = 8 warps; 64 queries/block; candidate tiles of 128.
// warp w: qg = w&3 (16 q rows), mh = w>>2 (64-m half).
// Each lane's partition: cols {mh*64 + nb*8 + (l&3)*2 + {0,1}} over all tiles
//   -> 8 disjoint partitions per query row; union of top-8s -> g_short[64].
__global__ __launch_bounds__(256) void k_knn_mma()
{
  __shared__ __nv_bfloat16 Qs[64*72];
  __shared__ __nv_bfloat16 Ds[128*72];

  int t = threadIdx.x, w = t >> 5, l = t & 31;
  int qg = w & 3, mh = w >> 2;
  int dir = blockIdx.z, b = blockIdx.y;
  int qbase = blockIdx.x * 64;

  const uint4* Qb = (const uint4*)(dir ? g_kb16[1] : g_kb16[0]);
  const uint4* Db = (const uint4*)(dir ? g_kb16[0] : g_kb16[1]);

  // load Q tile: 64 rows x 8 chunks (16B) each
  #pragma unroll
  for (int i = 0; i < 2; i++) {
    int id = t + i*256;
    int row = id >> 3, ck = id & 7;
    *(uint4*)&Qs[row*72 + ck*8] = Qb[(size_t)(b*NN + qbase + row)*8 + ck];
  }
  __syncthreads();

  // A fragments (Q), loaded once: 4 ksteps x 4 b32
  unsigned af[4][4];
  {
    int r0 = qg*16 + (l >> 2);
    #pragma unroll
    for (int ks = 0; ks < 4; ks++) {
      int kk = ks*16 + (l & 3)*2;
      af[ks][0] = *(const unsigned*)&Qs[r0*72 + kk];
      af[ks][1] = *(const unsigned*)&Qs[(r0+8)*72 + kk];
      af[ks][2] = *(const unsigned*)&Qs[r0*72 + kk + 8];
      af[ks][3] = *(const unsigned*)&Qs[(r0+8)*72 + kk + 8];
    }
  }

  float d0[8], d1[8]; int i0[8], i1[8];
  #pragma unroll
  for (int i = 0; i < 8; i++) { d0[i] = -FLT_MAX; d1[i] = -FLT_MAX; i0[i] = 0; i1[i] = 0; }

  for (int mb = 0; mb < NN; mb += 128) {
    __syncthreads();
    #pragma unroll
    for (int i = 0; i < 4; i++) {
      int id = t + i*256;
      int row = id >> 3, ck = id & 7;
      *(uint4*)&Ds[row*72 + ck*8] = Db[(size_t)(b*NN + mb + row)*8 + ck];
    }
    __syncthreads();

    #pragma unroll
    for (int nb = 0; nb < 8; nb++) {
      float c0 = 0.f, c1 = 0.f, c2 = 0.f, c3 = 0.f;
      int n = mh*64 + nb*8 + (l >> 2);
      #pragma unroll
      for (int ks = 0; ks < 4; ks++) {
        int kk = ks*16 + (l & 3)*2;
        unsigned b0 = *(const unsigned*)&Ds[n*72 + kk];
        unsigned b1 = *(const unsigned*)&Ds[n*72 + kk + 8];
        asm volatile(
          "mma.sync.aligned.m16n8k16.row.col.f32.bf16.bf16.f32 "
          "{%0,%1,%2,%3}, {%4,%5,%6,%7}, {%8,%9}, {%0,%1,%2,%3};"
          : "+f"(c0), "+f"(c1), "+f"(c2), "+f"(c3)
          : "r"(af[ks][0]), "r"(af[ks][1]), "r"(af[ks][2]), "r"(af[ks][3]),
            "r"(b0), "r"(b1));
      }
      int base = mb + mh*64 + nb*8 + (l & 3)*2;
      INSMAX8(d0, i0, c0, base);
      INSMAX8(d0, i0, c1, base + 1);
      INSMAX8(d1, i1, c2, base);
      INSMAX8(d1, i1, c3, base + 1);
    }
  }

  // write shortlist: slot s = mh*4 + (l&3); rows r0 and r0+8
  {
    int q0 = qbase + qg*16 + (l >> 2);
    int s = mh*4 + (l & 3);
    int gb0 = ((dir*BB + b)*NN + q0)*64 + s*8;
    int gb1 = ((dir*BB + b)*NN + q0 + 8)*64 + s*8;
    #pragma unroll
    for (int i = 0; i < 8; i++) { g_short[gb0 + i] = i0[i]; g_short[gb1 + i] = i1[i]; }
  }
}

// ------ cosine KNN stage 2: exact fp32 re-rank of 64 candidates -----------
// 1 warp per query; lane holds cands l and l+32.
__global__ __launch_bounds__(256) void k_rerank()
{
  int dir = blockIdx.z, b = blockIdx.y;
  int w = threadIdx.x >> 5, l = threadIdx.x & 31;
  int q = blockIdx.x*8 + w;
  const float4* Qp = (const float4*)(dir ? g_knp[1] : g_knp[0]);
  const float4* Dp = (const float4*)(dir ? g_knp[0] : g_knp[1]);

  int gb = ((dir*BB + b)*NN + q)*64;
  int cA = g_short[gb + l];
  int cB = g_short[gb + 32 + l];

  const float4* qr = Qp + (size_t)(b*NN + q)*16;
  const float4* rA = Dp + (size_t)(b*NN + cA)*16;
  const float4* rB = Dp + (size_t)(b*NN + cB)*16;
  float dotA = 0.f, dotB = 0.f;
  #pragma unroll
  for (int c4 = 0; c4 < 16; c4++) {
    float4 a = qr[c4];
    float4 xA = rA[c4], xB = rB[c4];
    dotA += a.x*xA.x + a.y*xA.y + a.z*xA.z + a.w*xA.w;
    dotB += a.x*xB.x + a.y*xB.y + a.z*xB.z + a.w*xB.w;
  }
  float dA = 1.0f - dotA, dB = 1.0f - dotB;

  int go = ((dir*BB + b)*NN + q)*16;
  for (int r = 0; r < 8; r++) {
    float bd; int bi;
    if (dA < dB || (dA == dB && cA < cB)) { bd = dA; bi = cA; }
    else                                  { bd = dB; bi = cB; }
    #pragma unroll
    for (int off = 16; off > 0; off >>= 1) {
      float od = __shfl_xor_sync(0xffffffffu, bd, off);
      int   oi = __shfl_xor_sync(0xffffffffu, bi, off);
      if (od < bd || (od == bd && oi < bi)) { bd = od; bi = oi; }
    }
    if (l == 0) g_idx[go + r] = bi;
    if (cA == bi) dA = FLT_MAX;
    if (cB == bi) dB = FLT_MAX;
  }
}

// --------- euclid KNN: 4 threads/query, blocked ranges, smem merge --------
__global__ __launch_bounds__(256) void k_euclid()
{
  int dir = blockIdx.z, b = blockIdx.y;
  int qbase = blockIdx.x * 64;
  const float4* Qx = dir ? g_xyz[1] : g_xyz[0];
  const float4* Dx = dir ? g_xyz[0] : g_xyz[1];
  int t = threadIdx.x;
  int ql = t >> 2, sl = t & 3;
  int q = qbase + ql;

  float4 qx = Qx[b*NN + q];
  float dE[8]; int iE[8];
  #pragma unroll
  for (int i = 0; i < 8; i++) { dE[i] = FLT_MAX; iE[i] = -1; }

  const float4* base = &Dx[b*NN + sl*1024];
  #pragma unroll 4
  for (int i = 0; i < 1024; i++) {
    float4 d = __ldg(&base[i]);
    float de = qx.w + d.w - 2.0f*(qx.x*d.x + qx.y*d.y + qx.z*d.z);
    INSERT8(dE, iE, de, sl*1024 + i);
  }

  __shared__ float mD[2048];
  __shared__ int   mI[2048];
  #pragma unroll
  for (int i = 0; i < 8; i++) { mD[t*8 + i] = dE[i]; mI[t*8 + i] = iE[i]; }
  __syncthreads();
  if (t < 64) {
    int mb = t*32;
    int gb = ((dir*BB + b)*NN + qbase + t)*16 + 8;
    for (int r = 0; r < 8; r++) {
      float bd = FLT_MAX; int bs = 0;
      #pragma unroll
      for (int s2 = 0; s2 < 32; s2++) {
        float v = mD[mb + s2];
        if (v < bd) { bd = v; bs = s2; }
      }
      g_idx[gb + r] = mI[mb + bs];
      mD[mb + bs] = FLT_MAX;
    }
  }
}

// ------ gather + pos-MLP + 2x MLP + maxpool (unchanged from R12 best) -----
__global__ __launch_bounds__(256, 2) void k_mlp(
    const float* __restrict__ Wpos, const float* __restrict__ bpos,
    const float* __restrict__ Wm1,  const float* __restrict__ b1,
    const float* __restrict__ Wm2,  const float* __restrict__ b2,
    float* __restrict__ out)
{
  extern __shared__ float sm[];
  float* sW1  = sm;
  float* sW2  = sm + 4352;
  float* bufA = sm + 8704;
  float* bufB = sm + 17152;
  float* sP1  = sm + 25600;
  float4* sPos = (float4*)(sm + 26112);
  float* sB1  = sm + 26368;
  float* sB2  = sm + 26432;
  float4* sDir = (float4*)(sm + 26496);
  int*   sNb  = (int*)(sm + 27008);

  int dir = blockIdx.z, b = blockIdx.y;
  int n0 = blockIdx.x * 8;
  const float* p1 = dir ? g_f2b : g_f1a;
  const float* p2 = dir ? g_f1b : g_f2a;
  const float4* Qx = dir ? g_xyz[1] : g_xyz[0];
  const float4* Dx = dir ? g_xyz[0] : g_xyz[1];

  int t = threadIdx.x;

  #pragma unroll
  for (int i = 0; i < 16; i++) {
    int idx = t + i*256;
    int e = idx >> 6, c = idx & 63;
    sW1[c*68 + e] = Wm1[idx];
    sW2[c*68 + e] = Wm2[idx];
  }
  if (t < 64) {
    sPos[t] = make_float4(Wpos[t*3], Wpos[t*3+1], Wpos[t*3+2], bpos[t]);
    sB1[t] = b1[t];
    sB2[t] = b2[t];
  }
  #pragma unroll
  for (int i = 0; i < 2; i++) {
    int idx = t + i*256;
    int q = idx >> 6, d = idx & 63;
    sP1[idx] = p1[(b*NN + n0 + q)*64 + d];
  }
  if (t < 128) {
    int q = t >> 4, k = t & 15;
    int nb = g_idx[((dir*BB + b)*NN + n0 + q)*16 + k];
    sNb[t] = nb;
    float4 dxv = Dx[b*NN + nb], qxv = Qx[b*NN + n0 + q];
    sDir[t] = make_float4(dxv.x - qxv.x, dxv.y - qxv.y, dxv.z - qxv.z, 0.f);
  }
  __syncthreads();

  {
    int row = t & 127, half = t >> 7;
    int nb = sNb[row];
    int q = row >> 4;
    float4 dv = sDir[row];
    const float4* p2row = (const float4*)&p2[(b*NN + nb)*64] + half*8;
    const float* p1row = &sP1[q*64 + half*32];
    #pragma unroll
    for (int j = 0; j < 8; j++) {
      int d = half*32 + j*4;
      float4 g = p2row[j];
      float4 w0 = sPos[d+0], w1 = sPos[d+1], w2 = sPos[d+2], w3 = sPos[d+3];
      float v0 = g.x + p1row[j*4+0] + (dv.x*w0.x + dv.y*w0.y + dv.z*w0.z + w0.w);
      float v1 = g.y + p1row[j*4+1] + (dv.x*w1.x + dv.y*w1.y + dv.z*w1.z + w1.w);
      float v2 = g.z + p1row[j*4+2] + (dv.x*w2.x + dv.y*w2.y + dv.z*w2.z + w2.w);
      float v3 = g.w + p1row[j*4+3] + (dv.x*w3.x + dv.y*w3.y + dv.z*w3.z + w3.w);
      bufA[(d+0)*132 + row] = leaky(v0);
      bufA[(d+1)*132 + row] = leaky(v1);
      bufA[(d+2)*132 + row] = leaky(v2);
      bufA[(d+3)*132 + row] = leaky(v3);
    }
  }
  __syncthreads();

  int rq = t >> 4, tm = t & 15;
  int r0 = rq*8;

  {
    u64 acc[4][4];
    #pragma unroll
    for (int i = 0; i < 4; i++)
      #pragma unroll
      for (int j = 0; j < 4; j++) acc[i][j] = 0ULL;
    #pragma unroll 4
    for (int c = 0; c < 64; c++) {
      float wv0 = sW1[c*68 + tm];
      float wv1 = sW1[c*68 + tm + 16];
      float wv2 = sW1[c*68 + tm + 32];
      float wv3 = sW1[c*68 + tm + 48];
      ulonglong2 ra = *(const ulonglong2*)&bufA[c*132 + r0];
      ulonglong2 rb = *(const ulonglong2*)&bufA[c*132 + r0 + 4];
      u64 w0 = pk2(wv0, wv0), w1 = pk2(wv1, wv1);
      u64 w2 = pk2(wv2, wv2), w3 = pk2(wv3, wv3);
      fma2(acc[0][0], ra.x, w0); fma2(acc[0][1], ra.x, w1);
      fma2(acc[0][2], ra.x, w2); fma2(acc[0][3], ra.x, w3);
      fma2(acc[1][0], ra.y, w0); fma2(acc[1][1], ra.y, w1);
      fma2(acc[1][2], ra.y, w2); fma2(acc[1][3], ra.y, w3);
      fma2(acc[2][0], rb.x, w0); fma2(acc[2][1], rb.x, w1);
      fma2(acc[2][2], rb.x, w2); fma2(acc[2][3], rb.x, w3);
      fma2(acc[3][0], rb.y, w0); fma2(acc[3][1], rb.y, w1);
      fma2(acc[3][2], rb.y, w2); fma2(acc[3][3], rb.y, w3);
    }
    #pragma unroll
    for (int j = 0; j < 4; j++) {
      int e = tm + 16*j;
      float bb = sB1[e];
      float2 v01 = up2(acc[0][j]), v23 = up2(acc[1][j]);
      float2 v45 = up2(acc[2][j]), v67 = up2(acc[3][j]);
      float4 lo = make_float4(leaky(v01.x+bb), leaky(v01.y+bb),
                              leaky(v23.x+bb), leaky(v23.y+bb));
      float4 hi = make_float4(leaky(v45.x+bb), leaky(v45.y+bb),
                              leaky(v67.x+bb), leaky(v67.y+bb));
      *(float4*)&bufB[e*132 + r0]     = lo;
      *(float4*)&bufB[e*132 + r0 + 4] = hi;
    }
  }
  __syncthreads();

  {
    u64 acc[4][4];
    #pragma unroll
    for (int i = 0; i < 4; i++)
      #pragma unroll
      for (int j = 0; j < 4; j++) acc[i][j] = 0ULL;
    #pragma unroll 4
    for (int c = 0; c < 64; c++) {
      float wv0 = sW2[c*68 + tm];
      float wv1 = sW2[c*68 + tm + 16];
      float wv2 = sW2[c*68 + tm + 32];
      float wv3 = sW2[c*68 + tm + 48];
      ulonglong2 ra = *(const ulonglong2*)&bufB[c*132 + r0];
      ulonglong2 rb = *(const ulonglong2*)&bufB[c*132 + r0 + 4];
      u64 w0 = pk2(wv0, wv0), w1 = pk2(wv1, wv1);
      u64 w2 = pk2(wv2, wv2), w3 = pk2(wv3, wv3);
      fma2(acc[0][0], ra.x, w0); fma2(acc[0][1], ra.x, w1);
      fma2(acc[0][2], ra.x, w2); fma2(acc[0][3], ra.x, w3);
      fma2(acc[1][0], ra.y, w0); fma2(acc[1][1], ra.y, w1);
      fma2(acc[1][2], ra.y, w2); fma2(acc[1][3], ra.y, w3);
      fma2(acc[2][0], rb.x, w0); fma2(acc[2][1], rb.x, w1);
      fma2(acc[2][2], rb.x, w2); fma2(acc[2][3], rb.x, w3);
      fma2(acc[3][0], rb.y, w0); fma2(acc[3][1], rb.y, w1);
      fma2(acc[3][2], rb.y, w2); fma2(acc[3][3], rb.y, w3);
    }
    float mj[4];
    #pragma unroll
    for (int j = 0; j < 4; j++) {
      int e = tm + 16*j;
      float bb = sB2[e];
      float2 v01 = up2(acc[0][j]), v23 = up2(acc[1][j]);
      float2 v45 = up2(acc[2][j]), v67 = up2(acc[3][j]);
      float m = fmaxf(fmaxf(leaky(v01.x+bb), leaky(v01.y+bb)),
                      fmaxf(leaky(v23.x+bb), leaky(v23.y+bb)));
      m = fmaxf(m, fmaxf(fmaxf(leaky(v45.x+bb), leaky(v45.y+bb)),
                         fmaxf(leaky(v67.x+bb), leaky(v67.y+bb))));
      mj[j] = m;
    }
    #pragma unroll
    for (int j = 0; j < 4; j++) {
      float o = __shfl_xor_sync(0xffffffffu, mj[j], 16);
      mj[j] = fmaxf(mj[j], o);
    }
    if ((rq & 1) == 0) {
      int q = rq >> 1;
      long obase = (long)dir*(BB*64*NN) + (long)b*(64*NN) + (n0 + q);
      #pragma unroll
      for (int j = 0; j < 4; j++) {
        int e = tm + 16*j;
        out[obase + (long)e*NN] = mj[j];
      }
    }
  }
}

// ---------------- launch ---------------------------------------------------
extern "C" void kernel_launch(void* const* d_in, const int* in_sizes, int n_in,
                              void* d_out, int out_size)
{
  const float* pc1   = (const float*)d_in[0];
  const float* pc2   = (const float*)d_in[1];
  const float* feat1 = (const float*)d_in[2];
  const float* feat2 = (const float*)d_in[3];
  const float* knn1  = (const float*)d_in[4];
  const float* knn2  = (const float*)d_in[5];
  const float* W11   = (const float*)d_in[6];
  const float* b11   = (const float*)d_in[7];
  const float* W22   = (const float*)d_in[8];
  const float* b22   = (const float*)d_in[9];
  const float* Wpos  = (const float*)d_in[10];
  const float* bpos  = (const float*)d_in[11];
  const float* Wm1   = (const float*)d_in[12];
  const float* bm1   = (const float*)d_in[13];
  const float* Wm2   = (const float*)d_in[14];
  const float* bm2   = (const float*)d_in[15];
  float* out = (float*)d_out;

  cudaFuncSetAttribute(k_mlp, cudaFuncAttributeMaxDynamicSharedMemorySize, 108544);

  k_transform<<<dim3(64, 2, 4), 256>>>(feat1, feat2, W11, b11, W22, b22);
  k_normalize<<<dim3(64, 2, 2), 256>>>(knn1, knn2);
  k_xyz<<<dim3(16, 2, 2), 256>>>(pc1, pc2);
  k_knn_mma<<<dim3(64, 2, 2), 256>>>();
  k_rerank<<<dim3(512, 2, 2), 256>>>();
  k_euclid<<<dim3(64, 2, 2), 256>>>();
  k_mlp<<<dim3(512, 2, 2), 256, 108544>>>(Wpos, bpos, Wm1, bm1, Wm2, bm2, out);
}